// round 2
// baseline (speedup 1.0000x reference)
#include <cuda_runtime.h>
#include <cstdint>
#include <cstddef>

// Problem constants (fixed shapes from the reference)
constexpr int Bc  = 4;
constexpr int Sc  = 2048;
constexpr int Dc  = 1024;
constexpr int Hc  = 16;
constexpr int DKc = 64;
constexpr long long BSD  = (long long)Bc * Sc * Dc;                 // 8,388,608
constexpr long long BHSS = (long long)Bc * Hc * Sc * Sc;            // 268,435,456

// Scratch (static __device__ arrays: allocation-free, graph-safe)
__device__ float g_q[Bc * Sc * Dc];
__device__ float g_k[Bc * Sc * Dc];
__device__ float g_v[Bc * Sc * Dc];
__device__ float g_ctx[Bc * Sc * Dc];
// Fallback home for attn if the harness output does not include it
__device__ float g_attn[(size_t)Bc * Hc * Sc * Sc];

#define TBM 64
#define TBN 64
#define TBK 16

// ---------------------------------------------------------------------------
// Generic NT GEMM: C[M,N] = alpha * A[M,K] @ B[N,K]^T + bias
// Both A and B are K-major (k contiguous). Tiles assumed to divide evenly.
// ---------------------------------------------------------------------------
__global__ __launch_bounds__(256) void gemm_nt_kernel(
    const float* __restrict__ A, const float* __restrict__ B,
    float* __restrict__ C, const float* __restrict__ bias,
    int M, int N, int K, int lda, int ldb, int ldc, float alpha)
{
    __shared__ __align__(16) float As[TBK][TBM + 4];
    __shared__ __align__(16) float Bs[TBK][TBN + 4];

    const int tid = threadIdx.x;
    const int tx  = tid & 15;
    const int ty  = tid >> 4;
    const int m0  = blockIdx.y * TBM;
    const int n0  = blockIdx.x * TBN;

    const int lr = tid >> 2;          // 0..63: row within tile
    const int lk = (tid & 3) << 2;    // 0,4,8,12: k offset (float4)

    const float* Ap = A + (size_t)(m0 + lr) * lda + lk;
    const float* Bp = B + (size_t)(n0 + lr) * ldb + lk;

    float acc[4][4] = {};

    for (int k0 = 0; k0 < K; k0 += TBK) {
        float4 av = *(const float4*)(Ap + k0);
        float4 bv = *(const float4*)(Bp + k0);
        As[lk + 0][lr] = av.x; As[lk + 1][lr] = av.y;
        As[lk + 2][lr] = av.z; As[lk + 3][lr] = av.w;
        Bs[lk + 0][lr] = bv.x; Bs[lk + 1][lr] = bv.y;
        Bs[lk + 2][lr] = bv.z; Bs[lk + 3][lr] = bv.w;
        __syncthreads();
#pragma unroll
        for (int kk = 0; kk < TBK; kk++) {
            float4 a4 = *(const float4*)&As[kk][ty * 4];
            float4 b4 = *(const float4*)&Bs[kk][tx * 4];
            float ar[4] = {a4.x, a4.y, a4.z, a4.w};
            float br[4] = {b4.x, b4.y, b4.z, b4.w};
#pragma unroll
            for (int i = 0; i < 4; i++)
#pragma unroll
                for (int j = 0; j < 4; j++)
                    acc[i][j] += ar[i] * br[j];
        }
        __syncthreads();
    }

    float4 bvec = make_float4(0.f, 0.f, 0.f, 0.f);
    if (bias) bvec = *(const float4*)(bias + n0 + tx * 4);
#pragma unroll
    for (int i = 0; i < 4; i++) {
        float* crow = C + (size_t)(m0 + ty * 4 + i) * ldc + n0 + tx * 4;
        float4 r;
        r.x = acc[i][0] * alpha + bvec.x;
        r.y = acc[i][1] * alpha + bvec.y;
        r.z = acc[i][2] * alpha + bvec.z;
        r.w = acc[i][3] * alpha + bvec.w;
        *(float4*)crow = r;
    }
}

// ---------------------------------------------------------------------------
// Scores: per (b,h): S_scores = (q @ k^T) / 8, written to attn[(b*H+h)*S*S]
// q,k live in [B,S,D] layout, head slice stride Dc.
// ---------------------------------------------------------------------------
__global__ __launch_bounds__(256) void scores_kernel(float* __restrict__ attn)
{
    __shared__ __align__(16) float As[TBK][TBM + 4];
    __shared__ __align__(16) float Bs[TBK][TBN + 4];

    const int z = blockIdx.z;            // b*H + h
    const int b = z >> 4;
    const int h = z & 15;
    const float* A = g_q + (size_t)b * Sc * Dc + h * DKc;
    const float* B = g_k + (size_t)b * Sc * Dc + h * DKc;
    float* C = attn + (size_t)z * Sc * Sc;

    const int tid = threadIdx.x;
    const int tx  = tid & 15;
    const int ty  = tid >> 4;
    const int m0  = blockIdx.y * TBM;
    const int n0  = blockIdx.x * TBN;
    const int lr  = tid >> 2;
    const int lk  = (tid & 3) << 2;

    const float* Ap = A + (size_t)(m0 + lr) * Dc + lk;
    const float* Bp = B + (size_t)(n0 + lr) * Dc + lk;

    float acc[4][4] = {};
#pragma unroll
    for (int k0 = 0; k0 < DKc; k0 += TBK) {
        float4 av = *(const float4*)(Ap + k0);
        float4 bv = *(const float4*)(Bp + k0);
        As[lk + 0][lr] = av.x; As[lk + 1][lr] = av.y;
        As[lk + 2][lr] = av.z; As[lk + 3][lr] = av.w;
        Bs[lk + 0][lr] = bv.x; Bs[lk + 1][lr] = bv.y;
        Bs[lk + 2][lr] = bv.z; Bs[lk + 3][lr] = bv.w;
        __syncthreads();
#pragma unroll
        for (int kk = 0; kk < TBK; kk++) {
            float4 a4 = *(const float4*)&As[kk][ty * 4];
            float4 b4 = *(const float4*)&Bs[kk][tx * 4];
            float ar[4] = {a4.x, a4.y, a4.z, a4.w};
            float br[4] = {b4.x, b4.y, b4.z, b4.w};
#pragma unroll
            for (int i = 0; i < 4; i++)
#pragma unroll
                for (int j = 0; j < 4; j++)
                    acc[i][j] += ar[i] * br[j];
        }
        __syncthreads();
    }

    const float alpha = 0.125f;  // 1/sqrt(64)
#pragma unroll
    for (int i = 0; i < 4; i++) {
        float* crow = C + (size_t)(m0 + ty * 4 + i) * Sc + n0 + tx * 4;
        float4 r;
        r.x = acc[i][0] * alpha;
        r.y = acc[i][1] * alpha;
        r.z = acc[i][2] * alpha;
        r.w = acc[i][3] * alpha;
        *(float4*)crow = r;
    }
}

// ---------------------------------------------------------------------------
// In-place softmax over rows of length Sc (=2048). One block per row.
// ---------------------------------------------------------------------------
__global__ __launch_bounds__(256) void softmax_kernel(float* __restrict__ attn)
{
    float* p = attn + (size_t)blockIdx.x * Sc;
    const int tid = threadIdx.x;

    float4 a = *(const float4*)(p + tid * 4);
    float4 bq = *(const float4*)(p + 1024 + tid * 4);
    float x[8] = {a.x, a.y, a.z, a.w, bq.x, bq.y, bq.z, bq.w};

    float m = x[0];
#pragma unroll
    for (int i = 1; i < 8; i++) m = fmaxf(m, x[i]);
#pragma unroll
    for (int o = 16; o > 0; o >>= 1) m = fmaxf(m, __shfl_xor_sync(0xffffffffu, m, o));

    __shared__ float red[8];
    if ((tid & 31) == 0) red[tid >> 5] = m;
    __syncthreads();
    float bm = red[0];
#pragma unroll
    for (int i = 1; i < 8; i++) bm = fmaxf(bm, red[i]);

    float s = 0.f;
#pragma unroll
    for (int i = 0; i < 8; i++) { x[i] = __expf(x[i] - bm); s += x[i]; }
#pragma unroll
    for (int o = 16; o > 0; o >>= 1) s += __shfl_xor_sync(0xffffffffu, s, o);
    __syncthreads();
    if ((tid & 31) == 0) red[tid >> 5] = s;
    __syncthreads();
    float bs = 0.f;
#pragma unroll
    for (int i = 0; i < 8; i++) bs += red[i];

    float inv = 1.0f / bs;
    a.x  = x[0] * inv; a.y  = x[1] * inv; a.z  = x[2] * inv; a.w  = x[3] * inv;
    bq.x = x[4] * inv; bq.y = x[5] * inv; bq.z = x[6] * inv; bq.w = x[7] * inv;
    *(float4*)(p + tid * 4)        = a;
    *(float4*)(p + 1024 + tid * 4) = bq;
}

// ---------------------------------------------------------------------------
// Ctx: per (b,h): ctx = attn[z] @ v_head   (NN GEMM: A k-contiguous, B [K,N])
// ctx written in [B,S,D] layout at column offset h*64.
// ---------------------------------------------------------------------------
__global__ __launch_bounds__(256) void ctx_kernel(const float* __restrict__ attn)
{
    __shared__ __align__(16) float As[TBK][TBM + 4];
    __shared__ __align__(16) float Bs[TBK][TBN + 4];

    const int z = blockIdx.z;
    const int b = z >> 4;
    const int h = z & 15;
    const float* A = attn + (size_t)z * Sc * Sc;          // [S, S]
    const float* B = g_v + (size_t)b * Sc * Dc + h * DKc; // [S, 64], row stride Dc
    float* C = g_ctx + (size_t)b * Sc * Dc + h * DKc;     // row stride Dc

    const int tid = threadIdx.x;
    const int tx  = tid & 15;
    const int ty  = tid >> 4;
    const int m0  = blockIdx.y * TBM;     // N tile fixed (N=64 → one tile)

    const int lr = tid >> 2;              // A-load: row 0..63, k float4
    const int lk = (tid & 3) << 2;
    const float* Ap = A + (size_t)(m0 + lr) * Sc + lk;

    const int brow  = tid >> 4;           // B-load: k row 0..15
    const int bcol4 = (tid & 15) << 2;    // n offset, float4
    const float* Bp = B + (size_t)brow * Dc + bcol4;

    float acc[4][4] = {};
    for (int k0 = 0; k0 < Sc; k0 += TBK) {
        float4 av = *(const float4*)(Ap + k0);
        float4 bv = *(const float4*)(Bp + (size_t)k0 * Dc);
        As[lk + 0][lr] = av.x; As[lk + 1][lr] = av.y;
        As[lk + 2][lr] = av.z; As[lk + 3][lr] = av.w;
        *(float4*)&Bs[brow][bcol4] = bv;
        __syncthreads();
#pragma unroll
        for (int kk = 0; kk < TBK; kk++) {
            float4 a4 = *(const float4*)&As[kk][ty * 4];
            float4 b4 = *(const float4*)&Bs[kk][tx * 4];
            float ar[4] = {a4.x, a4.y, a4.z, a4.w};
            float br[4] = {b4.x, b4.y, b4.z, b4.w};
#pragma unroll
            for (int i = 0; i < 4; i++)
#pragma unroll
                for (int j = 0; j < 4; j++)
                    acc[i][j] += ar[i] * br[j];
        }
        __syncthreads();
    }

#pragma unroll
    for (int i = 0; i < 4; i++) {
        float* crow = C + (size_t)(m0 + ty * 4 + i) * Dc + tx * 4;
        *(float4*)crow = make_float4(acc[i][0], acc[i][1], acc[i][2], acc[i][3]);
    }
}

// ---------------------------------------------------------------------------
// Host launch
// ---------------------------------------------------------------------------
extern "C" void kernel_launch(void* const* d_in, const int* in_sizes, int n_in,
                              void* d_out, int out_size)
{
    const float* Q  = (const float*)d_in[0];
    const float* K  = (const float*)d_in[1];
    const float* V  = (const float*)d_in[2];
    const float* wq = (const float*)d_in[3];
    const float* bq = (const float*)d_in[4];
    const float* wk = (const float*)d_in[5];
    const float* bk = (const float*)d_in[6];
    const float* wv = (const float*)d_in[7];
    const float* bv = (const float*)d_in[8];
    const float* wo = (const float*)d_in[9];
    const float* bo = (const float*)d_in[10];
    float* out = (float*)d_out;

    float *qp, *kp, *vp, *cp, *attn_scratch;
    cudaGetSymbolAddress((void**)&qp, g_q);
    cudaGetSymbolAddress((void**)&kp, g_k);
    cudaGetSymbolAddress((void**)&vp, g_v);
    cudaGetSymbolAddress((void**)&cp, g_ctx);
    cudaGetSymbolAddress((void**)&attn_scratch, g_attn);

    // attn output location: harness output tail if present, else scratch
    float* attn = ((long long)out_size >= BSD + BHSS) ? (out + BSD) : attn_scratch;

    const int M = Bc * Sc;  // 8192

    dim3 blk(256);
    dim3 gProj(Dc / TBN, M / TBM);             // (16, 128)
    dim3 gScore(Sc / TBN, Sc / TBM, Bc * Hc);  // (32, 32, 64)
    dim3 gCtx(1, Sc / TBM, Bc * Hc);           // (1, 32, 64)
    dim3 gSm(Bc * Hc * Sc);                    // 131072 rows

    // Projections
    gemm_nt_kernel<<<gProj, blk>>>(Q, wq, qp, bq, M, Dc, Dc, Dc, Dc, Dc, 1.0f);
    gemm_nt_kernel<<<gProj, blk>>>(K, wk, kp, bk, M, Dc, Dc, Dc, Dc, Dc, 1.0f);
    gemm_nt_kernel<<<gProj, blk>>>(V, wv, vp, bv, M, Dc, Dc, Dc, Dc, Dc, 1.0f);

    // Attention
    scores_kernel<<<gScore, blk>>>(attn);
    softmax_kernel<<<gSm, blk>>>(attn);
    ctx_kernel<<<gCtx, blk>>>(attn);

    // Output projection
    gemm_nt_kernel<<<gProj, blk>>>(cp, wo, out, bo, M, Dc, Dc, Dc, Dc, Dc, 1.0f);
}

// round 9
// speedup vs baseline: 1.9972x; 1.9972x over previous
#include <cuda_runtime.h>
#include <cstdint>
#include <cstddef>

constexpr int Bc  = 4;
constexpr int Sc  = 2048;
constexpr int Dc  = 1024;
constexpr int Hc  = 16;
constexpr int DKc = 64;
constexpr long long BSD  = (long long)Bc * Sc * Dc;       // 8,388,608
constexpr long long BHSS = (long long)Bc * Hc * Sc * Sc;  // 268,435,456

// Scratch (allocation-free, graph-safe)
__device__ float g_q[Bc * Sc * Dc];
__device__ float g_k[Bc * Sc * Dc];
__device__ float g_v[Bc * Sc * Dc];
__device__ float g_ctx[Bc * Sc * Dc];
__device__ float g_attn[(size_t)Bc * Hc * Sc * Sc];

// ---------------------------------------------------------------------------
// tf32 helpers
// ---------------------------------------------------------------------------
__device__ __forceinline__ uint32_t f2tf(float x) {
    uint32_t u;
    asm("cvt.rna.tf32.f32 %0, %1;" : "=r"(u) : "f"(x));
    return u;
}

__device__ __forceinline__ void mma_tf32(float* c, const uint32_t* a, const uint32_t* b) {
    asm volatile(
        "mma.sync.aligned.m16n8k8.row.col.f32.tf32.tf32.f32 "
        "{%0,%1,%2,%3},{%4,%5,%6,%7},{%8,%9},{%0,%1,%2,%3};"
        : "+f"(c[0]), "+f"(c[1]), "+f"(c[2]), "+f"(c[3])
        : "r"(a[0]), "r"(a[1]), "r"(a[2]), "r"(a[3]), "r"(b[0]), "r"(b[1]));
}

// ---------------------------------------------------------------------------
// Batched tf32 MMA GEMM.
//   C[M,N] = alpha * A @ op(B) + bias
//   A: [M,K] row-major (k contiguous), leading dim lda
//   B: BT=true  -> [N,K] k-contiguous (NT gemm), leading dim ldb
//      BT=false -> [K,N] n-contiguous (NN gemm), leading dim ldb
//   blockIdx.z decodes (b = z>>4, h = z&15); per-tensor offsets via bs*/hs*.
// ---------------------------------------------------------------------------
template<int BM, int BN, int WM, int WN, bool BT>
__global__ __launch_bounds__(256) void mma_gemm(
    const float* __restrict__ A, const float* __restrict__ B,
    float* __restrict__ C, const float* __restrict__ bias,
    int M, int N, int K, int lda, int ldb, int ldc,
    long long bsA, long long hsA, long long bsB, long long hsB,
    long long bsC, long long hsC, float alpha)
{
    constexpr int BK  = 16;
    constexpr int WTM = BM / WM;     // warp tile M
    constexpr int WTN = BN / WN;     // warp tile N
    constexpr int MT  = WTM / 16;    // m16 tiles per warp
    constexpr int NT  = WTN / 8;     // n8 tiles per warp

    __shared__ uint32_t As[BK][BM + 8];
    __shared__ uint32_t Bs[BK][BN + 8];

    const int zb = blockIdx.z >> 4;
    const int zh = blockIdx.z & 15;
    const float* Ab = A + zb * bsA + zh * hsA;
    const float* Bb = B + zb * bsB + zh * hsB;
    float*       Cb = C + zb * bsC + zh * hsC;

    const int tid  = threadIdx.x;
    const int warp = tid >> 5;
    const int lane = tid & 31;
    const int g    = lane >> 2;   // groupID 0..7
    const int tg   = lane & 3;    // thread-in-group 0..3

    const int wm = warp % WM;
    const int wn = warp / WM;

    const int m0 = blockIdx.y * BM;
    const int n0 = blockIdx.x * BN;

    const float* Ap = Ab + (size_t)m0 * lda;
    const float* Bp = BT ? (Bb + (size_t)n0 * ldb) : (Bb + n0);

    float acc[MT][NT][4] = {};

    for (int k0 = 0; k0 < K; k0 += BK) {
        // ---- load A tile [BM x 16] into As[k][m] (transposed, tf32) ----
        constexpr int LA = (BM * BK) / (4 * 256);
#pragma unroll
        for (int i = 0; i < LA; i++) {
            int idx = tid + i * 256;           // float4 index
            int row = idx >> 2;
            int kq  = (idx & 3) * 4;
            float4 v = *(const float4*)(Ap + (size_t)row * lda + k0 + kq);
            As[kq + 0][row] = f2tf(v.x);
            As[kq + 1][row] = f2tf(v.y);
            As[kq + 2][row] = f2tf(v.z);
            As[kq + 3][row] = f2tf(v.w);
        }
        // ---- load B tile into Bs[k][n] ----
        if (BT) {
            constexpr int LB = (BN * BK) / (4 * 256);
#pragma unroll
            for (int i = 0; i < LB; i++) {
                int idx = tid + i * 256;
                int row = idx >> 2;            // n index
                int kq  = (idx & 3) * 4;
                float4 v = *(const float4*)(Bp + (size_t)row * ldb + k0 + kq);
                Bs[kq + 0][row] = f2tf(v.x);
                Bs[kq + 1][row] = f2tf(v.y);
                Bs[kq + 2][row] = f2tf(v.z);
                Bs[kq + 3][row] = f2tf(v.w);
            }
        } else {
            constexpr int LB = (BK * BN) / (4 * 256);
#pragma unroll
            for (int i = 0; i < LB; i++) {
                int idx  = tid + i * 256;
                int krow = idx / (BN / 4);
                int nq   = (idx % (BN / 4)) * 4;
                float4 v = *(const float4*)(Bp + (size_t)(k0 + krow) * ldb + nq);
                Bs[krow][nq + 0] = f2tf(v.x);
                Bs[krow][nq + 1] = f2tf(v.y);
                Bs[krow][nq + 2] = f2tf(v.z);
                Bs[krow][nq + 3] = f2tf(v.w);
            }
        }
        __syncthreads();

        // ---- two k8 MMA sub-steps ----
#pragma unroll
        for (int ks = 0; ks < 2; ks++) {
            const int kk = ks * 8 + tg;
            uint32_t afrag[MT][4];
            uint32_t bfrag[NT][2];
#pragma unroll
            for (int i = 0; i < MT; i++) {
                int m = wm * WTM + i * 16 + g;
                afrag[i][0] = As[kk    ][m];
                afrag[i][1] = As[kk    ][m + 8];
                afrag[i][2] = As[kk + 4][m];
                afrag[i][3] = As[kk + 4][m + 8];
            }
#pragma unroll
            for (int j = 0; j < NT; j++) {
                int n = wn * WTN + j * 8 + g;
                bfrag[j][0] = Bs[kk    ][n];
                bfrag[j][1] = Bs[kk + 4][n];
            }
#pragma unroll
            for (int i = 0; i < MT; i++)
#pragma unroll
                for (int j = 0; j < NT; j++)
                    mma_tf32(acc[i][j], afrag[i], bfrag[j]);
        }
        __syncthreads();
    }

    // ---- epilogue ----
#pragma unroll
    for (int i = 0; i < MT; i++) {
#pragma unroll
        for (int j = 0; j < NT; j++) {
            int row = m0 + wm * WTM + i * 16 + g;
            int col = n0 + wn * WTN + j * 8 + 2 * tg;
            float b0 = 0.f, b1 = 0.f;
            if (bias) { b0 = bias[col]; b1 = bias[col + 1]; }
            float2 v0, v1;
            v0.x = acc[i][j][0] * alpha + b0;
            v0.y = acc[i][j][1] * alpha + b1;
            v1.x = acc[i][j][2] * alpha + b0;
            v1.y = acc[i][j][3] * alpha + b1;
            *(float2*)(Cb + (size_t)row * ldc + col)       = v0;
            *(float2*)(Cb + (size_t)(row + 8) * ldc + col) = v1;
        }
    }
}

// ---------------------------------------------------------------------------
// In-place softmax over rows of length 2048. One 256-thread block per row.
// ---------------------------------------------------------------------------
__global__ __launch_bounds__(256) void softmax_kernel(float* __restrict__ attn)
{
    float* p = attn + (size_t)blockIdx.x * Sc;
    const int tid = threadIdx.x;

    float4 a = *(const float4*)(p + tid * 4);
    float4 bq = *(const float4*)(p + 1024 + tid * 4);
    float x[8] = {a.x, a.y, a.z, a.w, bq.x, bq.y, bq.z, bq.w};

    float m = x[0];
#pragma unroll
    for (int i = 1; i < 8; i++) m = fmaxf(m, x[i]);
#pragma unroll
    for (int o = 16; o > 0; o >>= 1) m = fmaxf(m, __shfl_xor_sync(0xffffffffu, m, o));

    __shared__ float red[8];
    if ((tid & 31) == 0) red[tid >> 5] = m;
    __syncthreads();
    float bm = red[0];
#pragma unroll
    for (int i = 1; i < 8; i++) bm = fmaxf(bm, red[i]);

    float s = 0.f;
#pragma unroll
    for (int i = 0; i < 8; i++) { x[i] = __expf(x[i] - bm); s += x[i]; }
#pragma unroll
    for (int o = 16; o > 0; o >>= 1) s += __shfl_xor_sync(0xffffffffu, s, o);
    __syncthreads();
    if ((tid & 31) == 0) red[tid >> 5] = s;
    __syncthreads();
    float bs = 0.f;
#pragma unroll
    for (int i = 0; i < 8; i++) bs += red[i];

    float inv = 1.0f / bs;
    a.x  = x[0] * inv; a.y  = x[1] * inv; a.z  = x[2] * inv; a.w  = x[3] * inv;
    bq.x = x[4] * inv; bq.y = x[5] * inv; bq.z = x[6] * inv; bq.w = x[7] * inv;
    *(float4*)(p + tid * 4)        = a;
    *(float4*)(p + 1024 + tid * 4) = bq;
}

// ---------------------------------------------------------------------------
// Host launch
// ---------------------------------------------------------------------------
extern "C" void kernel_launch(void* const* d_in, const int* in_sizes, int n_in,
                              void* d_out, int out_size)
{
    const float* Q  = (const float*)d_in[0];
    const float* K  = (const float*)d_in[1];
    const float* V  = (const float*)d_in[2];
    const float* wq = (const float*)d_in[3];
    const float* bq = (const float*)d_in[4];
    const float* wk = (const float*)d_in[5];
    const float* bk = (const float*)d_in[6];
    const float* wv = (const float*)d_in[7];
    const float* bv = (const float*)d_in[8];
    const float* wo = (const float*)d_in[9];
    const float* bo = (const float*)d_in[10];
    float* out = (float*)d_out;

    float *qp, *kp, *vp, *cp, *attn_scratch;
    cudaGetSymbolAddress((void**)&qp, g_q);
    cudaGetSymbolAddress((void**)&kp, g_k);
    cudaGetSymbolAddress((void**)&vp, g_v);
    cudaGetSymbolAddress((void**)&cp, g_ctx);
    cudaGetSymbolAddress((void**)&attn_scratch, g_attn);

    float* attn = ((long long)out_size >= BSD + BHSS) ? (out + BSD) : attn_scratch;

    const int M = Bc * Sc;  // 8192
    dim3 blk(256);

    // Projections: C[8192,1024] = X @ W^T + b   (NT, no batch)
    dim3 gProj(Dc / 128, M / 128, 1);   // (8, 64)
    mma_gemm<128,128,2,4,true><<<gProj, blk>>>(Q, wq, qp, bq, M, Dc, Dc, Dc, Dc, Dc,
                                               0,0,0,0,0,0, 1.0f);
    mma_gemm<128,128,2,4,true><<<gProj, blk>>>(K, wk, kp, bk, M, Dc, Dc, Dc, Dc, Dc,
                                               0,0,0,0,0,0, 1.0f);
    mma_gemm<128,128,2,4,true><<<gProj, blk>>>(V, wv, vp, bv, M, Dc, Dc, Dc, Dc, Dc,
                                               0,0,0,0,0,0, 1.0f);

    // Scores: per (b,h) S = (q @ k^T)/8  (NT batched over z)
    dim3 gScore(Sc / 128, Sc / 128, Bc * Hc);   // (16, 16, 64)
    mma_gemm<128,128,2,4,true><<<gScore, blk>>>(qp, kp, attn, nullptr,
        Sc, Sc, DKc, Dc, Dc, Sc,
        (long long)Sc * Dc, DKc,            // A: b stride, h stride
        (long long)Sc * Dc, DKc,            // B
        (long long)Hc * Sc * Sc, (long long)Sc * Sc,  // C
        0.125f);

    // Softmax in place
    softmax_kernel<<<dim3(Bc * Hc * Sc), blk>>>(attn);

    // Ctx: per (b,h) ctx = attn @ v_head  (NN batched over z)
    dim3 gCtx(1, Sc / 128, Bc * Hc);            // (1, 16, 64)
    mma_gemm<128,64,4,2,false><<<gCtx, blk>>>(attn, vp, cp, nullptr,
        Sc, DKc, Sc, Sc, Dc, Dc,
        (long long)Hc * Sc * Sc, (long long)Sc * Sc,
        (long long)Sc * Dc, DKc,
        (long long)Sc * Dc, DKc,
        1.0f);

    // Output projection
    mma_gemm<128,128,2,4,true><<<gProj, blk>>>(cp, wo, out, bo, M, Dc, Dc, Dc, Dc, Dc,
                                               0,0,0,0,0,0, 1.0f);
}